// round 13
// baseline (speedup 1.0000x reference)
#include <cuda_runtime.h>
#include <cuda_fp16.h>
#include <math.h>
#include <stdint.h>

#define B_ 512
#define T_ 256
#define E_ 384
#define H_ 64
#define M_ (B_ * T_)   // 131072

// Projected q,k,v stored as fp16
__device__ __half g_q[(size_t)M_ * H_];
__device__ __half g_k[(size_t)M_ * H_];
__device__ __half g_v[(size_t)M_ * H_];
__device__ __half g_wh[192 * 384];   // W^T fp16: [n][k], n = m*64+h

__device__ __forceinline__ unsigned pack_h2(float lo, float hi) {
    unsigned d;
    asm("cvt.rn.f16x2.f32 %0, %1, %2;" : "=r"(d) : "f"(hi), "f"(lo));
    return d;
}
__device__ __forceinline__ uint32_t s2u(const void* p) {
    uint32_t a;
    asm("{ .reg .u64 t; cvta.to.shared.u64 t, %1; cvt.u32.u64 %0, t; }"
        : "=r"(a) : "l"(p));
    return a;
}
__device__ __forceinline__ void cpa16(uint32_t dst, const void* src) {
    asm volatile("cp.async.cg.shared.global [%0], [%1], 16;"
                 :: "r"(dst), "l"(src) : "memory");
}

#define MMA_F16(C, A, B0, B1)                                               \
    asm volatile(                                                           \
        "mma.sync.aligned.m16n8k16.row.col.f32.f16.f16.f32 "                \
        "{%0,%1,%2,%3}, {%4,%5,%6,%7}, {%8,%9}, {%0,%1,%2,%3};"             \
        : "+f"((C)[0]), "+f"((C)[1]), "+f"((C)[2]), "+f"((C)[3])            \
        : "r"((A)[0]), "r"((A)[1]), "r"((A)[2]), "r"((A)[3]),               \
          "r"(B0), "r"(B1))

#define LDM_X4(R0, R1, R2, R3, ADDR)                                        \
    asm volatile("ldmatrix.sync.aligned.m8n8.x4.shared.b16 "                \
                 "{%0,%1,%2,%3}, [%4];"                                     \
                 : "=r"(R0), "=r"(R1), "=r"(R2), "=r"(R3) : "r"(ADDR))

#define LDM_X4_T(R0, R1, R2, R3, ADDR)                                      \
    asm volatile("ldmatrix.sync.aligned.m8n8.x4.trans.shared.b16 "          \
                 "{%0,%1,%2,%3}, [%4];"                                     \
                 : "=r"(R0), "=r"(R1), "=r"(R2), "=r"(R3) : "r"(ADDR))

// ---------------------------------------------------------------------------
// Kernel 0: W -> fp16, layout g_wh[n][k]  (n = m*64 + h)
// ---------------------------------------------------------------------------
__global__ __launch_bounds__(256) void wh_kernel(
    const float* __restrict__ Wq, const float* __restrict__ Wk,
    const float* __restrict__ Wv)
{
    int idx = blockIdx.x * 256 + threadIdx.x;
    int n = idx / 384, k = idx % 384;
    const float* Wm = (n < 64) ? Wq : ((n < 128) ? Wk : Wv);
    g_wh[idx] = __float2half_rn(Wm[(size_t)k * 64 + (n & 63)]);
}

// ---------------------------------------------------------------------------
// Kernel 1: fused QKV projection, fp16 mma + ldmatrix, 2 CTAs/SM.
// CTA: 64 rows x 192 cols, 256 threads, 8 warps, warp tile 32x48.
// smem: Xh[2][64][40] | Wh[2][192][40]  (40 KB total)
// Pipeline (one barrier per chunk, race-free):
//   wait_group 0 ; __syncthreads() ; issue next LDG+cp.async ; mma ; stsX(next)
// ---------------------------------------------------------------------------
#define XST_SZ   (64 * 40)             // 2560 halves per stage
#define WST_OFF  (2 * XST_SZ)          // 5120
#define WST_SZ   (192 * 40)            // 7680 halves per stage
#define QKV_SMEM_BYTES ((2 * XST_SZ + 2 * WST_SZ) * 2)   // 40960

__global__ __launch_bounds__(256, 2) void qkv_fp16_kernel(const float* __restrict__ x)
{
    extern __shared__ __align__(16) __half smq[];
    const uint32_t sb = s2u(smq);
    __half* Xh = smq;

    const int tid  = threadIdx.x;
    const int warp = tid >> 5;
    const int lane = tid & 31;
    const int lrow = lane & 7;
    const int row0 = blockIdx.x * 64;

    const int mbase = (warp >> 2) * 32;   // 0, 32
    const int nbase = (warp & 3) * 48;    // 0,48,96,144

    const float* xp = x + (size_t)row0 * E_;

    const int xr  = tid >> 2;             // 0..63
    const int xc8 = (tid & 3) * 8;

    auto prefetchW = [&](int s, int kb) {
        const uint32_t wb = sb + (WST_OFF + s * WST_SZ) * 2;
        #pragma unroll
        for (int i = 0; i < 3; i++) {      // 768 x 16B
            int f = tid + i * 256;
            int n = f >> 2, cc = f & 3;
            cpa16(wb + (n * 40 + cc * 8) * 2,
                  g_wh + (size_t)n * 384 + kb * 32 + cc * 8);
        }
        asm volatile("cp.async.commit_group;" ::: "memory");
    };
    auto stsX = [&](int s, const float4& a, const float4& bq) {
        uint4 p;
        p.x = pack_h2(a.x, a.y);
        p.y = pack_h2(a.z, a.w);
        p.z = pack_h2(bq.x, bq.y);
        p.w = pack_h2(bq.z, bq.w);
        *(uint4*)(Xh + s * XST_SZ + xr * 40 + xc8) = p;
    };

    // prologue: chunk 0
    {
        const float* src = xp + (size_t)xr * E_ + xc8;
        float4 xa = *(const float4*)src;
        float4 xb = *(const float4*)(src + 4);
        prefetchW(0, 0);
        stsX(0, xa, xb);
    }

    float c[2][6][4] = {};

    #pragma unroll 1
    for (int kb = 0; kb < 12; kb++) {
        const int s = kb & 1;

        // chunk kb's W copies (committed last iteration / prologue) must land
        asm volatile("cp.async.wait_group 0;" ::: "memory");
        __syncthreads();   // publish W cp.asyncs + X stores of stage s to all warps

        // issue next chunk's loads (overlap with this chunk's mma)
        float4 xa2, xb2;
        if (kb + 1 < 12) {
            const float* src = xp + (size_t)xr * E_ + (kb + 1) * 32 + xc8;
            xa2 = *(const float4*)src;
            xb2 = *(const float4*)(src + 4);
            prefetchW(s ^ 1, kb + 1);
        }

        const uint32_t xbse = sb + (s * XST_SZ) * 2;
        const uint32_t wbse = sb + (WST_OFF + s * WST_SZ) * 2;

        #pragma unroll
        for (int kc = 0; kc < 2; kc++) {
            const int kk = kc * 16;
            unsigned a[2][4];
            #pragma unroll
            for (int mt = 0; mt < 2; mt++) {
                uint32_t addr = xbse + 2 * ((mbase + mt * 16
                                             + ((lane >> 3) & 1) * 8
                                             + lrow) * 40
                                            + kk + (lane >> 4) * 8);
                LDM_X4(a[mt][0], a[mt][1], a[mt][2], a[mt][3], addr);
            }
            #pragma unroll
            for (int ntp = 0; ntp < 3; ntp++) {
                unsigned b0, b1, b2, b3;
                uint32_t addr = wbse + 2 * ((nbase + ntp * 16
                                             + (lane >> 4) * 8
                                             + lrow) * 40
                                            + kk + ((lane >> 3) & 1) * 8);
                LDM_X4(b0, b1, b2, b3, addr);
                MMA_F16(c[0][2 * ntp],     a[0], b0, b1);
                MMA_F16(c[1][2 * ntp],     a[1], b0, b1);
                MMA_F16(c[0][2 * ntp + 1], a[0], b2, b3);
                MMA_F16(c[1][2 * ntp + 1], a[1], b2, b3);
            }
        }

        // stage s^1 was last READ in iteration kb-1; every warp passed this
        // iteration's barrier after finishing it -> safe to overwrite now.
        if (kb + 1 < 12) stsX(s ^ 1, xa2, xb2);
    }

    // Epilogue: pack fp32 accum -> fp16
    const int g = lane >> 2;
    const int t = lane & 3;
    #pragma unroll
    for (int mt = 0; mt < 2; mt++) {
        #pragma unroll
        for (int nt = 0; nt < 6; nt++) {
            int col = nbase + nt * 8 + 2 * t;
            int m = col >> 6;
            int h = col & 63;
            __half* o = (m == 0) ? g_q : ((m == 1) ? g_k : g_v);
            int r = row0 + mbase + mt * 16 + g;
            *(unsigned*)&o[(size_t)r * H_ + h]       = pack_h2(c[mt][nt][0], c[mt][nt][1]);
            *(unsigned*)&o[(size_t)(r + 8) * H_ + h] = pack_h2(c[mt][nt][2], c[mt][nt][3]);
        }
    }
}

// ---------------------------------------------------------------------------
// Kernel 2: flash attention, fp16 mma + ldmatrix (R8/R9 version, ~43us).
// ---------------------------------------------------------------------------
#define ASTR   72
#define KS_OFF 0
#define VS_OFF (64 * ASTR)
#define QS_OFF (128 * ASTR)
#define ATTN_SMEM_BYTES ((256 * ASTR) * 2)   // 36864

__global__ __launch_bounds__(256, 2) void attn_fp16_kernel(float* __restrict__ out)
{
    extern __shared__ __align__(16) __half smh[];
    const uint32_t sb = s2u(smh);
    __half* Ks = smh + KS_OFF;
    __half* Vs = smh + VS_OFF;
    __half* Qs = smh + QS_OFF;
    unsigned* Qu = (unsigned*)Qs;

    const int tid  = threadIdx.x;
    const int warp = tid >> 5;
    const int lane = tid & 31;
    const int g    = lane >> 2;
    const int t    = lane & 3;
    const int q0   = blockIdx.x * 128;
    const int b    = blockIdx.y;

    const __half* qp = g_q + ((size_t)b * T_ + q0) * H_;
    const __half2 sc = __float2half2_rn(0.125f);
    #pragma unroll
    for (int i = 0; i < 4; i++) {
        int f = tid + i * 256;
        int r = f >> 3, h8 = (f & 7) * 8;
        uint4 v = *(const uint4*)(qp + (size_t)r * 64 + h8);
        __half2* hv = (__half2*)&v;
        hv[0] = __hmul2(hv[0], sc); hv[1] = __hmul2(hv[1], sc);
        hv[2] = __hmul2(hv[2], sc); hv[3] = __hmul2(hv[3], sc);
        *(uint4*)(Qs + r * ASTR + h8) = v;
    }
    __syncthreads();

    const int lr = warp * 16 + g;
    unsigned qf[4][4];
    #pragma unroll
    for (int s = 0; s < 4; s++) {
        qf[s][0] = Qu[lr * 36 + 8 * s + t];
        qf[s][1] = Qu[(lr + 8) * 36 + 8 * s + t];
        qf[s][2] = Qu[lr * 36 + 8 * s + t + 4];
        qf[s][3] = Qu[(lr + 8) * 36 + 8 * s + t + 4];
    }

    float o[8][4] = {};
    float m0 = -1e30f, m1 = -1e30f, l0 = 0.0f, l1 = 0.0f;

    const int row_min = q0 + warp * 16;
    const int row_max = row_min + 15;
    const int r0g = row_min + g;
    const int ktmax = (q0 + 127) >> 6;

    const __half* kp = g_k + (size_t)b * T_ * H_;
    const __half* vp = g_v + (size_t)b * T_ * H_;

    const int lrow = lane & 7;
    const int lmat = lane >> 3;

    for (int kt = 0; kt <= ktmax; kt++) {
        #pragma unroll
        for (int i = 0; i < 2; i++) {
            int f = tid + i * 256;
            int c = f >> 3, h8 = (f & 7) * 8;
            *(uint4*)(Ks + c * ASTR + h8) =
                *(const uint4*)(kp + (size_t)(kt * 64 + c) * 64 + h8);
            *(uint4*)(Vs + c * ASTR + h8) =
                *(const uint4*)(vp + (size_t)(kt * 64 + c) * 64 + h8);
        }
        __syncthreads();

        if (kt * 64 <= row_max) {
            float s[8][4] = {};
            #pragma unroll
            for (int nt = 0; nt < 8; nt++) {
                #pragma unroll
                for (int jj = 0; jj < 2; jj++) {
                    uint32_t addr = sb + 2 * (KS_OFF + (nt * 8 + lrow) * ASTR
                                              + 32 * jj + 8 * lmat);
                    unsigned r0, r1, r2, r3;
                    LDM_X4(r0, r1, r2, r3, addr);
                    MMA_F16(s[nt], qf[2 * jj],     r0, r1);
                    MMA_F16(s[nt], qf[2 * jj + 1], r2, r3);
                }
            }

            if (kt * 64 + 63 > row_min) {
                int colb = kt * 64 + 2 * t;
                #pragma unroll
                for (int nt = 0; nt < 8; nt++) {
                    int c0 = colb + nt * 8, c1 = c0 + 1;
                    if (c0 > r0g)     s[nt][0] = -1e30f;
                    if (c1 > r0g)     s[nt][1] = -1e30f;
                    if (c0 > r0g + 8) s[nt][2] = -1e30f;
                    if (c1 > r0g + 8) s[nt][3] = -1e30f;
                }
            }

            float mx0 = -1e30f, mx1 = -1e30f;
            #pragma unroll
            for (int nt = 0; nt < 8; nt++) {
                mx0 = fmaxf(mx0, fmaxf(s[nt][0], s[nt][1]));
                mx1 = fmaxf(mx1, fmaxf(s[nt][2], s[nt][3]));
            }
            mx0 = fmaxf(mx0, __shfl_xor_sync(0xffffffffu, mx0, 1));
            mx0 = fmaxf(mx0, __shfl_xor_sync(0xffffffffu, mx0, 2));
            mx1 = fmaxf(mx1, __shfl_xor_sync(0xffffffffu, mx1, 1));
            mx1 = fmaxf(mx1, __shfl_xor_sync(0xffffffffu, mx1, 2));

            float mn0 = fmaxf(m0, mx0), mn1 = fmaxf(m1, mx1);
            float cr0 = __expf(m0 - mn0), cr1 = __expf(m1 - mn1);
            float sum0 = 0.0f, sum1 = 0.0f;
            #pragma unroll
            for (int nt = 0; nt < 8; nt++) {
                s[nt][0] = __expf(s[nt][0] - mn0);
                s[nt][1] = __expf(s[nt][1] - mn0);
                s[nt][2] = __expf(s[nt][2] - mn1);
                s[nt][3] = __expf(s[nt][3] - mn1);
                sum0 += s[nt][0] + s[nt][1];
                sum1 += s[nt][2] + s[nt][3];
            }
            sum0 += __shfl_xor_sync(0xffffffffu, sum0, 1);
            sum0 += __shfl_xor_sync(0xffffffffu, sum0, 2);
            sum1 += __shfl_xor_sync(0xffffffffu, sum1, 1);
            sum1 += __shfl_xor_sync(0xffffffffu, sum1, 2);

            l0 = l0 * cr0 + sum0;  l1 = l1 * cr1 + sum1;
            m0 = mn0;              m1 = mn1;
            #pragma unroll
            for (int nt = 0; nt < 8; nt++) {
                o[nt][0] *= cr0; o[nt][1] *= cr0;
                o[nt][2] *= cr1; o[nt][3] *= cr1;
            }

            unsigned af[4][4];
            #pragma unroll
            for (int j = 0; j < 4; j++) {
                af[j][0] = pack_h2(s[2 * j][0],     s[2 * j][1]);
                af[j][1] = pack_h2(s[2 * j][2],     s[2 * j][3]);
                af[j][2] = pack_h2(s[2 * j + 1][0], s[2 * j + 1][1]);
                af[j][3] = pack_h2(s[2 * j + 1][2], s[2 * j + 1][3]);
            }

            #pragma unroll
            for (int nt = 0; nt < 8; nt++) {
                #pragma unroll
                for (int jj = 0; jj < 2; jj++) {
                    uint32_t addr = sb + 2 * (VS_OFF
                                              + (32 * jj + 8 * lmat + lrow) * ASTR
                                              + 8 * nt);
                    unsigned r0, r1, r2, r3;
                    LDM_X4_T(r0, r1, r2, r3, addr);
                    MMA_F16(o[nt], af[2 * jj],     r0, r1);
                    MMA_F16(o[nt], af[2 * jj + 1], r2, r3);
                }
            }
        }
        __syncthreads();
    }

    float inv0 = 1.0f / l0, inv1 = 1.0f / l1;
    float* op0 = out + ((size_t)b * T_ + q0 + lr) * 64;
    float* op1 = out + ((size_t)b * T_ + q0 + lr + 8) * 64;
    #pragma unroll
    for (int nt = 0; nt < 8; nt++) {
        int col = nt * 8 + 2 * t;
        *(float2*)&op0[col] = make_float2(o[nt][0] * inv0, o[nt][1] * inv0);
        *(float2*)&op1[col] = make_float2(o[nt][2] * inv1, o[nt][3] * inv1);
    }
}

// ---------------------------------------------------------------------------
extern "C" void kernel_launch(void* const* d_in, const int* in_sizes, int n_in,
                              void* d_out, int out_size)
{
    const float* x  = (const float*)d_in[0];
    const float* Wq = (const float*)d_in[1];
    const float* Wk = (const float*)d_in[2];
    const float* Wv = (const float*)d_in[3];
    float* out = (float*)d_out;

    wh_kernel<<<288, 256>>>(Wq, Wk, Wv);

    cudaFuncSetAttribute(qkv_fp16_kernel,
                         cudaFuncAttributeMaxDynamicSharedMemorySize,
                         QKV_SMEM_BYTES);
    qkv_fp16_kernel<<<M_ / 64, 256, QKV_SMEM_BYTES>>>(x);

    cudaFuncSetAttribute(attn_fp16_kernel,
                         cudaFuncAttributeMaxDynamicSharedMemorySize,
                         ATTN_SMEM_BYTES);
    attn_fp16_kernel<<<dim3(T_ / 128, B_), 256, ATTN_SMEM_BYTES>>>(out);
}

// round 14
// speedup vs baseline: 1.1503x; 1.1503x over previous
#include <cuda_runtime.h>
#include <cuda_fp16.h>
#include <math.h>
#include <stdint.h>

#define B_ 512
#define T_ 256
#define E_ 384
#define H_ 64
#define M_ (B_ * T_)   // 131072

// Projected q,k,v stored as fp16
__device__ __half g_q[(size_t)M_ * H_];
__device__ __half g_k[(size_t)M_ * H_];
__device__ __half g_v[(size_t)M_ * H_];
__device__ __half g_wh[192 * 384];   // W^T fp16: [n][k], n = m*64+h

__device__ __forceinline__ unsigned pack_h2(float lo, float hi) {
    unsigned d;
    asm("cvt.rn.f16x2.f32 %0, %1, %2;" : "=r"(d) : "f"(hi), "f"(lo));
    return d;
}
__device__ __forceinline__ uint32_t s2u(const void* p) {
    uint32_t a;
    asm("{ .reg .u64 t; cvta.to.shared.u64 t, %1; cvt.u32.u64 %0, t; }"
        : "=r"(a) : "l"(p));
    return a;
}
__device__ __forceinline__ void cpa16(uint32_t dst, const void* src) {
    asm volatile("cp.async.cg.shared.global [%0], [%1], 16;"
                 :: "r"(dst), "l"(src) : "memory");
}

#define MMA_F16(C, A, B0, B1)                                               \
    asm volatile(                                                           \
        "mma.sync.aligned.m16n8k16.row.col.f32.f16.f16.f32 "                \
        "{%0,%1,%2,%3}, {%4,%5,%6,%7}, {%8,%9}, {%0,%1,%2,%3};"             \
        : "+f"((C)[0]), "+f"((C)[1]), "+f"((C)[2]), "+f"((C)[3])            \
        : "r"((A)[0]), "r"((A)[1]), "r"((A)[2]), "r"((A)[3]),               \
          "r"(B0), "r"(B1))

#define LDM_X4(R0, R1, R2, R3, ADDR)                                        \
    asm volatile("ldmatrix.sync.aligned.m8n8.x4.shared.b16 "                \
                 "{%0,%1,%2,%3}, [%4];"                                     \
                 : "=r"(R0), "=r"(R1), "=r"(R2), "=r"(R3) : "r"(ADDR))

#define LDM_X4_T(R0, R1, R2, R3, ADDR)                                      \
    asm volatile("ldmatrix.sync.aligned.m8n8.x4.trans.shared.b16 "          \
                 "{%0,%1,%2,%3}, [%4];"                                     \
                 : "=r"(R0), "=r"(R1), "=r"(R2), "=r"(R3) : "r"(ADDR))

// ---------------------------------------------------------------------------
// Kernel 0: W -> fp16, layout g_wh[n][k]  (n = m*64 + h)
// ---------------------------------------------------------------------------
__global__ __launch_bounds__(256) void wh_kernel(
    const float* __restrict__ Wq, const float* __restrict__ Wk,
    const float* __restrict__ Wv)
{
    int idx = blockIdx.x * 256 + threadIdx.x;
    int n = idx / 384, k = idx % 384;
    const float* Wm = (n < 64) ? Wq : ((n < 128) ? Wk : Wv);
    g_wh[idx] = __float2half_rn(Wm[(size_t)k * 64 + (n & 63)]);
}

// ---------------------------------------------------------------------------
// Kernel 1: fused QKV projection, fp16 mma + ldmatrix, Kc=64.
// CTA: 64 rows x 192 cols, 256 threads, 8 warps, warp tile 32x48, 2 CTAs/SM.
// 6 K-chunks of 64; one barrier + one wait per chunk; 48 mmas per warp
// per chunk (4 k16 blocks).
// smem: Xh[2][64][72] | Wh[2][192][72]  (73.7 KB)
// ---------------------------------------------------------------------------
#define QKSTR 72
#define XST_SZ   (64 * QKSTR)            // 4608 halves per stage
#define WST_OFF  (2 * XST_SZ)            // 9216
#define WST_SZ   (192 * QKSTR)           // 13824 halves per stage
#define QKV_SMEM_BYTES ((2 * XST_SZ + 2 * WST_SZ) * 2)   // 73728

__global__ __launch_bounds__(256, 2) void qkv_fp16_kernel(const float* __restrict__ x)
{
    extern __shared__ __align__(16) __half smq[];
    const uint32_t sb = s2u(smq);
    __half* Xh = smq;

    const int tid  = threadIdx.x;
    const int warp = tid >> 5;
    const int lane = tid & 31;
    const int lrow = lane & 7;
    const int row0 = blockIdx.x * 64;

    const int mbase = (warp >> 2) * 32;   // 0, 32
    const int nbase = (warp & 3) * 48;    // 0,48,96,144

    const float* xp = x + (size_t)row0 * E_;

    // X slice per thread: rows xr0, xr0+32; 8 consecutive floats at col xcf
    const int xr0 = tid >> 3;             // 0..31
    const int xcf = (tid & 7) * 8;        // 0..56

    auto prefetchW = [&](int s, int kb) {
        const uint32_t wb = sb + (WST_OFF + s * WST_SZ) * 2;
        #pragma unroll
        for (int i = 0; i < 6; i++) {      // 1536 x 16B
            int f = tid + i * 256;
            int n = f >> 3, cc = f & 7;
            cpa16(wb + (n * QKSTR + cc * 8) * 2,
                  g_wh + (size_t)n * 384 + kb * 64 + cc * 8);
        }
        asm volatile("cp.async.commit_group;" ::: "memory");
    };

    float4 xv[4];          // 16 floats: rows xr0 and xr0+32, 8 floats each
    auto ldgX = [&](int kb) {
        const float* s0 = xp + (size_t)xr0 * E_ + kb * 64 + xcf;
        const float* s1 = xp + (size_t)(xr0 + 32) * E_ + kb * 64 + xcf;
        xv[0] = *(const float4*)s0;
        xv[1] = *(const float4*)(s0 + 4);
        xv[2] = *(const float4*)s1;
        xv[3] = *(const float4*)(s1 + 4);
    };
    auto stsX = [&](int s) {
        uint4 p0, p1;
        p0.x = pack_h2(xv[0].x, xv[0].y);  p0.y = pack_h2(xv[0].z, xv[0].w);
        p0.z = pack_h2(xv[1].x, xv[1].y);  p0.w = pack_h2(xv[1].z, xv[1].w);
        p1.x = pack_h2(xv[2].x, xv[2].y);  p1.y = pack_h2(xv[2].z, xv[2].w);
        p1.z = pack_h2(xv[3].x, xv[3].y);  p1.w = pack_h2(xv[3].z, xv[3].w);
        *(uint4*)(Xh + s * XST_SZ + xr0 * QKSTR + xcf)        = p0;
        *(uint4*)(Xh + s * XST_SZ + (xr0 + 32) * QKSTR + xcf) = p1;
    };

    // prologue: chunk 0
    ldgX(0);
    prefetchW(0, 0);
    stsX(0);

    float c[2][6][4] = {};

    #pragma unroll 1
    for (int kb = 0; kb < 6; kb++) {
        const int s = kb & 1;

        asm volatile("cp.async.wait_group 0;" ::: "memory");
        __syncthreads();   // publish W cp.asyncs + X stores of stage s

        if (kb + 1 < 6) {
            ldgX(kb + 1);
            prefetchW(s ^ 1, kb + 1);
        }

        const uint32_t xbse = sb + (s * XST_SZ) * 2;
        const uint32_t wbse = sb + (WST_OFF + s * WST_SZ) * 2;

        #pragma unroll
        for (int kc = 0; kc < 4; kc++) {
            const int kk = kc * 16;
            unsigned a[2][4];
            #pragma unroll
            for (int mt = 0; mt < 2; mt++) {
                uint32_t addr = xbse + 2 * ((mbase + mt * 16
                                             + ((lane >> 3) & 1) * 8
                                             + lrow) * QKSTR
                                            + kk + (lane >> 4) * 8);
                LDM_X4(a[mt][0], a[mt][1], a[mt][2], a[mt][3], addr);
            }
            #pragma unroll
            for (int ntp = 0; ntp < 3; ntp++) {
                unsigned b0, b1, b2, b3;
                uint32_t addr = wbse + 2 * ((nbase + ntp * 16
                                             + (lane >> 4) * 8
                                             + lrow) * QKSTR
                                            + kk + ((lane >> 3) & 1) * 8);
                LDM_X4(b0, b1, b2, b3, addr);
                MMA_F16(c[0][2 * ntp],     a[0], b0, b1);
                MMA_F16(c[1][2 * ntp],     a[1], b0, b1);
                MMA_F16(c[0][2 * ntp + 1], a[0], b2, b3);
                MMA_F16(c[1][2 * ntp + 1], a[1], b2, b3);
            }
        }

        // stage s^1 last read in iteration kb-1; all warps passed this
        // iteration's barrier -> safe to overwrite.
        if (kb + 1 < 6) stsX(s ^ 1);
    }

    // Epilogue: pack fp32 accum -> fp16
    const int g = lane >> 2;
    const int t = lane & 3;
    #pragma unroll
    for (int mt = 0; mt < 2; mt++) {
        #pragma unroll
        for (int nt = 0; nt < 6; nt++) {
            int col = nbase + nt * 8 + 2 * t;
            int m = col >> 6;
            int h = col & 63;
            __half* o = (m == 0) ? g_q : ((m == 1) ? g_k : g_v);
            int r = row0 + mbase + mt * 16 + g;
            *(unsigned*)&o[(size_t)r * H_ + h]       = pack_h2(c[mt][nt][0], c[mt][nt][1]);
            *(unsigned*)&o[(size_t)(r + 8) * H_ + h] = pack_h2(c[mt][nt][2], c[mt][nt][3]);
        }
    }
}

// ---------------------------------------------------------------------------
// Kernel 2: flash attention, fp16 mma + ldmatrix (R8/R12 version, ~43us).
// ---------------------------------------------------------------------------
#define ASTR   72
#define KS_OFF 0
#define VS_OFF (64 * ASTR)
#define QS_OFF (128 * ASTR)
#define ATTN_SMEM_BYTES ((256 * ASTR) * 2)   // 36864

__global__ __launch_bounds__(256, 2) void attn_fp16_kernel(float* __restrict__ out)
{
    extern __shared__ __align__(16) __half smh[];
    const uint32_t sb = s2u(smh);
    __half* Ks = smh + KS_OFF;
    __half* Vs = smh + VS_OFF;
    __half* Qs = smh + QS_OFF;
    unsigned* Qu = (unsigned*)Qs;

    const int tid  = threadIdx.x;
    const int warp = tid >> 5;
    const int lane = tid & 31;
    const int g    = lane >> 2;
    const int t    = lane & 3;
    const int q0   = blockIdx.x * 128;
    const int b    = blockIdx.y;

    const __half* qp = g_q + ((size_t)b * T_ + q0) * H_;
    const __half2 sc = __float2half2_rn(0.125f);
    #pragma unroll
    for (int i = 0; i < 4; i++) {
        int f = tid + i * 256;
        int r = f >> 3, h8 = (f & 7) * 8;
        uint4 v = *(const uint4*)(qp + (size_t)r * 64 + h8);
        __half2* hv = (__half2*)&v;
        hv[0] = __hmul2(hv[0], sc); hv[1] = __hmul2(hv[1], sc);
        hv[2] = __hmul2(hv[2], sc); hv[3] = __hmul2(hv[3], sc);
        *(uint4*)(Qs + r * ASTR + h8) = v;
    }
    __syncthreads();

    const int lr = warp * 16 + g;
    unsigned qf[4][4];
    #pragma unroll
    for (int s = 0; s < 4; s++) {
        qf[s][0] = Qu[lr * 36 + 8 * s + t];
        qf[s][1] = Qu[(lr + 8) * 36 + 8 * s + t];
        qf[s][2] = Qu[lr * 36 + 8 * s + t + 4];
        qf[s][3] = Qu[(lr + 8) * 36 + 8 * s + t + 4];
    }

    float o[8][4] = {};
    float m0 = -1e30f, m1 = -1e30f, l0 = 0.0f, l1 = 0.0f;

    const int row_min = q0 + warp * 16;
    const int row_max = row_min + 15;
    const int r0g = row_min + g;
    const int ktmax = (q0 + 127) >> 6;

    const __half* kp = g_k + (size_t)b * T_ * H_;
    const __half* vp = g_v + (size_t)b * T_ * H_;

    const int lrow = lane & 7;
    const int lmat = lane >> 3;

    for (int kt = 0; kt <= ktmax; kt++) {
        #pragma unroll
        for (int i = 0; i < 2; i++) {
            int f = tid + i * 256;
            int c = f >> 3, h8 = (f & 7) * 8;
            *(uint4*)(Ks + c * ASTR + h8) =
                *(const uint4*)(kp + (size_t)(kt * 64 + c) * 64 + h8);
            *(uint4*)(Vs + c * ASTR + h8) =
                *(const uint4*)(vp + (size_t)(kt * 64 + c) * 64 + h8);
        }
        __syncthreads();

        if (kt * 64 <= row_max) {
            float s[8][4] = {};
            #pragma unroll
            for (int nt = 0; nt < 8; nt++) {
                #pragma unroll
                for (int jj = 0; jj < 2; jj++) {
                    uint32_t addr = sb + 2 * (KS_OFF + (nt * 8 + lrow) * ASTR
                                              + 32 * jj + 8 * lmat);
                    unsigned r0, r1, r2, r3;
                    LDM_X4(r0, r1, r2, r3, addr);
                    MMA_F16(s[nt], qf[2 * jj],     r0, r1);
                    MMA_F16(s[nt], qf[2 * jj + 1], r2, r3);
                }
            }

            if (kt * 64 + 63 > row_min) {
                int colb = kt * 64 + 2 * t;
                #pragma unroll
                for (int nt = 0; nt < 8; nt++) {
                    int c0 = colb + nt * 8, c1 = c0 + 1;
                    if (c0 > r0g)     s[nt][0] = -1e30f;
                    if (c1 > r0g)     s[nt][1] = -1e30f;
                    if (c0 > r0g + 8) s[nt][2] = -1e30f;
                    if (c1 > r0g + 8) s[nt][3] = -1e30f;
                }
            }

            float mx0 = -1e30f, mx1 = -1e30f;
            #pragma unroll
            for (int nt = 0; nt < 8; nt++) {
                mx0 = fmaxf(mx0, fmaxf(s[nt][0], s[nt][1]));
                mx1 = fmaxf(mx1, fmaxf(s[nt][2], s[nt][3]));
            }
            mx0 = fmaxf(mx0, __shfl_xor_sync(0xffffffffu, mx0, 1));
            mx0 = fmaxf(mx0, __shfl_xor_sync(0xffffffffu, mx0, 2));
            mx1 = fmaxf(mx1, __shfl_xor_sync(0xffffffffu, mx1, 1));
            mx1 = fmaxf(mx1, __shfl_xor_sync(0xffffffffu, mx1, 2));

            float mn0 = fmaxf(m0, mx0), mn1 = fmaxf(m1, mx1);
            float cr0 = __expf(m0 - mn0), cr1 = __expf(m1 - mn1);
            float sum0 = 0.0f, sum1 = 0.0f;
            #pragma unroll
            for (int nt = 0; nt < 8; nt++) {
                s[nt][0] = __expf(s[nt][0] - mn0);
                s[nt][1] = __expf(s[nt][1] - mn0);
                s[nt][2] = __expf(s[nt][2] - mn1);
                s[nt][3] = __expf(s[nt][3] - mn1);
                sum0 += s[nt][0] + s[nt][1];
                sum1 += s[nt][2] + s[nt][3];
            }
            sum0 += __shfl_xor_sync(0xffffffffu, sum0, 1);
            sum0 += __shfl_xor_sync(0xffffffffu, sum0, 2);
            sum1 += __shfl_xor_sync(0xffffffffu, sum1, 1);
            sum1 += __shfl_xor_sync(0xffffffffu, sum1, 2);

            l0 = l0 * cr0 + sum0;  l1 = l1 * cr1 + sum1;
            m0 = mn0;              m1 = mn1;
            #pragma unroll
            for (int nt = 0; nt < 8; nt++) {
                o[nt][0] *= cr0; o[nt][1] *= cr0;
                o[nt][2] *= cr1; o[nt][3] *= cr1;
            }

            unsigned af[4][4];
            #pragma unroll
            for (int j = 0; j < 4; j++) {
                af[j][0] = pack_h2(s[2 * j][0],     s[2 * j][1]);
                af[j][1] = pack_h2(s[2 * j][2],     s[2 * j][3]);
                af[j][2] = pack_h2(s[2 * j + 1][0], s[2 * j + 1][1]);
                af[j][3] = pack_h2(s[2 * j + 1][2], s[2 * j + 1][3]);
            }

            #pragma unroll
            for (int nt = 0; nt < 8; nt++) {
                #pragma unroll
                for (int jj = 0; jj < 2; jj++) {
                    uint32_t addr = sb + 2 * (VS_OFF
                                              + (32 * jj + 8 * lmat + lrow) * ASTR
                                              + 8 * nt);
                    unsigned r0, r1, r2, r3;
                    LDM_X4_T(r0, r1, r2, r3, addr);
                    MMA_F16(o[nt], af[2 * jj],     r0, r1);
                    MMA_F16(o[nt], af[2 * jj + 1], r2, r3);
                }
            }
        }
        __syncthreads();
    }

    float inv0 = 1.0f / l0, inv1 = 1.0f / l1;
    float* op0 = out + ((size_t)b * T_ + q0 + lr) * 64;
    float* op1 = out + ((size_t)b * T_ + q0 + lr + 8) * 64;
    #pragma unroll
    for (int nt = 0; nt < 8; nt++) {
        int col = nt * 8 + 2 * t;
        *(float2*)&op0[col] = make_float2(o[nt][0] * inv0, o[nt][1] * inv0);
        *(float2*)&op1[col] = make_float2(o[nt][2] * inv1, o[nt][3] * inv1);
    }
}

// ---------------------------------------------------------------------------
extern "C" void kernel_launch(void* const* d_in, const int* in_sizes, int n_in,
                              void* d_out, int out_size)
{
    const float* x  = (const float*)d_in[0];
    const float* Wq = (const float*)d_in[1];
    const float* Wk = (const float*)d_in[2];
    const float* Wv = (const float*)d_in[3];
    float* out = (float*)d_out;

    wh_kernel<<<288, 256>>>(Wq, Wk, Wv);

    cudaFuncSetAttribute(qkv_fp16_kernel,
                         cudaFuncAttributeMaxDynamicSharedMemorySize,
                         QKV_SMEM_BYTES);
    qkv_fp16_kernel<<<M_ / 64, 256, QKV_SMEM_BYTES>>>(x);

    cudaFuncSetAttribute(attn_fp16_kernel,
                         cudaFuncAttributeMaxDynamicSharedMemorySize,
                         ATTN_SMEM_BYTES);
    attn_fp16_kernel<<<dim3(T_ / 128, B_), 256, ATTN_SMEM_BYTES>>>(out);
}

// round 15
// speedup vs baseline: 1.2121x; 1.0537x over previous
#include <cuda_runtime.h>
#include <cuda_fp16.h>
#include <math.h>
#include <stdint.h>

#define B_ 512
#define T_ 256
#define E_ 384
#define H_ 64
#define M_ (B_ * T_)   // 131072

// Projected q,k,v stored as fp16
__device__ __half g_q[(size_t)M_ * H_];
__device__ __half g_k[(size_t)M_ * H_];
__device__ __half g_v[(size_t)M_ * H_];
__device__ __half g_wh[192 * 384];   // W^T fp16: [n][k], n = m*64+h

__device__ __forceinline__ unsigned pack_h2(float lo, float hi) {
    unsigned d;
    asm("cvt.rn.f16x2.f32 %0, %1, %2;" : "=r"(d) : "f"(hi), "f"(lo));
    return d;
}
__device__ __forceinline__ uint32_t s2u(const void* p) {
    uint32_t a;
    asm("{ .reg .u64 t; cvta.to.shared.u64 t, %1; cvt.u32.u64 %0, t; }"
        : "=r"(a) : "l"(p));
    return a;
}
__device__ __forceinline__ void cpa16(uint32_t dst, const void* src) {
    asm volatile("cp.async.cg.shared.global [%0], [%1], 16;"
                 :: "r"(dst), "l"(src) : "memory");
}

#define MMA_F16(C, A, B0, B1)                                               \
    asm volatile(                                                           \
        "mma.sync.aligned.m16n8k16.row.col.f32.f16.f16.f32 "                \
        "{%0,%1,%2,%3}, {%4,%5,%6,%7}, {%8,%9}, {%0,%1,%2,%3};"             \
        : "+f"((C)[0]), "+f"((C)[1]), "+f"((C)[2]), "+f"((C)[3])            \
        : "r"((A)[0]), "r"((A)[1]), "r"((A)[2]), "r"((A)[3]),               \
          "r"(B0), "r"(B1))

#define LDM_X4(R0, R1, R2, R3, ADDR)                                        \
    asm volatile("ldmatrix.sync.aligned.m8n8.x4.shared.b16 "                \
                 "{%0,%1,%2,%3}, [%4];"                                     \
                 : "=r"(R0), "=r"(R1), "=r"(R2), "=r"(R3) : "r"(ADDR))

#define LDM_X4_T(R0, R1, R2, R3, ADDR)                                      \
    asm volatile("ldmatrix.sync.aligned.m8n8.x4.trans.shared.b16 "          \
                 "{%0,%1,%2,%3}, [%4];"                                     \
                 : "=r"(R0), "=r"(R1), "=r"(R2), "=r"(R3) : "r"(ADDR))

// ---------------------------------------------------------------------------
// Kernel 0: W -> fp16, layout g_wh[n][k]  (n = m*64 + h)
// ---------------------------------------------------------------------------
__global__ __launch_bounds__(256) void wh_kernel(
    const float* __restrict__ Wq, const float* __restrict__ Wk,
    const float* __restrict__ Wv)
{
    int idx = blockIdx.x * 256 + threadIdx.x;
    int n = idx / 384, k = idx % 384;
    const float* Wm = (n < 64) ? Wq : ((n < 128) ? Wk : Wv);
    g_wh[idx] = __float2half_rn(Wm[(size_t)k * 64 + (n & 63)]);
}

// ---------------------------------------------------------------------------
// Kernel 1: fused QKV projection (unchanged from R13, ~75us).
// CTA: 64 rows x 192 cols, 256 threads, Kc=64, 2 CTAs/SM.
// ---------------------------------------------------------------------------
#define QKSTR 72
#define XST_SZ   (64 * QKSTR)
#define WST_OFF  (2 * XST_SZ)
#define WST_SZ   (192 * QKSTR)
#define QKV_SMEM_BYTES ((2 * XST_SZ + 2 * WST_SZ) * 2)   // 73728

__global__ __launch_bounds__(256, 2) void qkv_fp16_kernel(const float* __restrict__ x)
{
    extern __shared__ __align__(16) __half smq[];
    const uint32_t sb = s2u(smq);
    __half* Xh = smq;

    const int tid  = threadIdx.x;
    const int warp = tid >> 5;
    const int lane = tid & 31;
    const int lrow = lane & 7;
    const int row0 = blockIdx.x * 64;

    const int mbase = (warp >> 2) * 32;
    const int nbase = (warp & 3) * 48;

    const float* xp = x + (size_t)row0 * E_;

    const int xr0 = tid >> 3;
    const int xcf = (tid & 7) * 8;

    auto prefetchW = [&](int s, int kb) {
        const uint32_t wb = sb + (WST_OFF + s * WST_SZ) * 2;
        #pragma unroll
        for (int i = 0; i < 6; i++) {
            int f = tid + i * 256;
            int n = f >> 3, cc = f & 7;
            cpa16(wb + (n * QKSTR + cc * 8) * 2,
                  g_wh + (size_t)n * 384 + kb * 64 + cc * 8);
        }
        asm volatile("cp.async.commit_group;" ::: "memory");
    };

    float4 xv[4];
    auto ldgX = [&](int kb) {
        const float* s0 = xp + (size_t)xr0 * E_ + kb * 64 + xcf;
        const float* s1 = xp + (size_t)(xr0 + 32) * E_ + kb * 64 + xcf;
        xv[0] = *(const float4*)s0;
        xv[1] = *(const float4*)(s0 + 4);
        xv[2] = *(const float4*)s1;
        xv[3] = *(const float4*)(s1 + 4);
    };
    auto stsX = [&](int s) {
        uint4 p0, p1;
        p0.x = pack_h2(xv[0].x, xv[0].y);  p0.y = pack_h2(xv[0].z, xv[0].w);
        p0.z = pack_h2(xv[1].x, xv[1].y);  p0.w = pack_h2(xv[1].z, xv[1].w);
        p1.x = pack_h2(xv[2].x, xv[2].y);  p1.y = pack_h2(xv[2].z, xv[2].w);
        p1.z = pack_h2(xv[3].x, xv[3].y);  p1.w = pack_h2(xv[3].z, xv[3].w);
        *(uint4*)(Xh + s * XST_SZ + xr0 * QKSTR + xcf)        = p0;
        *(uint4*)(Xh + s * XST_SZ + (xr0 + 32) * QKSTR + xcf) = p1;
    };

    ldgX(0);
    prefetchW(0, 0);
    stsX(0);

    float c[2][6][4] = {};

    #pragma unroll 1
    for (int kb = 0; kb < 6; kb++) {
        const int s = kb & 1;

        asm volatile("cp.async.wait_group 0;" ::: "memory");
        __syncthreads();

        if (kb + 1 < 6) {
            ldgX(kb + 1);
            prefetchW(s ^ 1, kb + 1);
        }

        const uint32_t xbse = sb + (s * XST_SZ) * 2;
        const uint32_t wbse = sb + (WST_OFF + s * WST_SZ) * 2;

        #pragma unroll
        for (int kc = 0; kc < 4; kc++) {
            const int kk = kc * 16;
            unsigned a[2][4];
            #pragma unroll
            for (int mt = 0; mt < 2; mt++) {
                uint32_t addr = xbse + 2 * ((mbase + mt * 16
                                             + ((lane >> 3) & 1) * 8
                                             + lrow) * QKSTR
                                            + kk + (lane >> 4) * 8);
                LDM_X4(a[mt][0], a[mt][1], a[mt][2], a[mt][3], addr);
            }
            #pragma unroll
            for (int ntp = 0; ntp < 3; ntp++) {
                unsigned b0, b1, b2, b3;
                uint32_t addr = wbse + 2 * ((nbase + ntp * 16
                                             + (lane >> 4) * 8
                                             + lrow) * QKSTR
                                            + kk + ((lane >> 3) & 1) * 8);
                LDM_X4(b0, b1, b2, b3, addr);
                MMA_F16(c[0][2 * ntp],     a[0], b0, b1);
                MMA_F16(c[1][2 * ntp],     a[1], b0, b1);
                MMA_F16(c[0][2 * ntp + 1], a[0], b2, b3);
                MMA_F16(c[1][2 * ntp + 1], a[1], b2, b3);
            }
        }

        if (kb + 1 < 6) stsX(s ^ 1);
    }

    const int g = lane >> 2;
    const int t = lane & 3;
    #pragma unroll
    for (int mt = 0; mt < 2; mt++) {
        #pragma unroll
        for (int nt = 0; nt < 6; nt++) {
            int col = nbase + nt * 8 + 2 * t;
            int m = col >> 6;
            int h = col & 63;
            __half* o = (m == 0) ? g_q : ((m == 1) ? g_k : g_v);
            int r = row0 + mbase + mt * 16 + g;
            *(unsigned*)&o[(size_t)r * H_ + h]       = pack_h2(c[mt][nt][0], c[mt][nt][1]);
            *(unsigned*)&o[(size_t)(r + 8) * H_ + h] = pack_h2(c[mt][nt][2], c[mt][nt][3]);
        }
    }
}

// ---------------------------------------------------------------------------
// Kernel 2: flash attention, fp16 mma + ldmatrix + cp.async KV double buffer.
// grid (T/128, B), 256 threads, 8 warps, warp owns 16 q-rows, 2 CTAs/SM.
// smem half layout: KV[2] stages (each Ks[64][72] | Vs[64][72]) | Qs[128][72]
// Pipeline per kt: wait_group 0 ; __syncthreads ; prefetch(kt+1) ; compute(kt)
// ---------------------------------------------------------------------------
#define ASTR   72
#define KVSTG  (128 * ASTR)                  // halves per stage
#define AQS_OFF (2 * KVSTG)                  // Qs offset (halves)
#define ATTN_SMEM_BYTES ((2 * KVSTG + 128 * ASTR) * 2)   // 55296

__global__ __launch_bounds__(256, 2) void attn_fp16_kernel(float* __restrict__ out)
{
    extern __shared__ __align__(16) __half smh[];
    const uint32_t sb = s2u(smh);
    __half* Qs = smh + AQS_OFF;
    unsigned* Qu = (unsigned*)Qs;

    const int tid  = threadIdx.x;
    const int warp = tid >> 5;
    const int lane = tid & 31;
    const int g    = lane >> 2;
    const int t    = lane & 3;
    const int q0   = blockIdx.x * 128;
    const int b    = blockIdx.y;

    const __half* kp = g_k + (size_t)b * T_ * H_;
    const __half* vp = g_v + (size_t)b * T_ * H_;

    // KV prefetch: rows 0-63 = K tile, rows 64-127 = V tile (contiguous)
    auto prefetchKV = [&](int s, int kt) {
        const uint32_t base = sb + (s * KVSTG) * 2;
        #pragma unroll
        for (int i = 0; i < 4; i++) {
            int f = tid + i * 256;            // 0..1023
            int c = f >> 3, h8 = (f & 7) * 8; // c 0..127
            const __half* src = (c < 64)
                ? (kp + (size_t)(kt * 64 + c) * 64 + h8)
                : (vp + (size_t)(kt * 64 + (c - 64)) * 64 + h8);
            cpa16(base + (c * ASTR + h8) * 2, src);
        }
        asm volatile("cp.async.commit_group;" ::: "memory");
    };

    // stage Q (scaled), prefetch first KV tile
    prefetchKV(0, 0);
    const __half* qp = g_q + ((size_t)b * T_ + q0) * H_;
    const __half2 sc = __float2half2_rn(0.125f);
    #pragma unroll
    for (int i = 0; i < 4; i++) {
        int f = tid + i * 256;
        int r = f >> 3, h8 = (f & 7) * 8;
        uint4 v = *(const uint4*)(qp + (size_t)r * 64 + h8);
        __half2* hv = (__half2*)&v;
        hv[0] = __hmul2(hv[0], sc); hv[1] = __hmul2(hv[1], sc);
        hv[2] = __hmul2(hv[2], sc); hv[3] = __hmul2(hv[3], sc);
        *(uint4*)(Qs + r * ASTR + h8) = v;
    }
    __syncthreads();   // publish Qs

    const int lr = warp * 16 + g;
    unsigned qf[4][4];
    #pragma unroll
    for (int s = 0; s < 4; s++) {
        qf[s][0] = Qu[lr * 36 + 8 * s + t];
        qf[s][1] = Qu[(lr + 8) * 36 + 8 * s + t];
        qf[s][2] = Qu[lr * 36 + 8 * s + t + 4];
        qf[s][3] = Qu[(lr + 8) * 36 + 8 * s + t + 4];
    }

    float o[8][4] = {};
    float m0 = -1e30f, m1 = -1e30f, l0 = 0.0f, l1 = 0.0f;

    const int row_min = q0 + warp * 16;
    const int row_max = row_min + 15;
    const int r0g = row_min + g;
    const int ktmax = (q0 + 127) >> 6;

    const int lrow = lane & 7;
    const int lmat = lane >> 3;

    #pragma unroll 1
    for (int kt = 0; kt <= ktmax; kt++) {
        const int st = kt & 1;

        asm volatile("cp.async.wait_group 0;" ::: "memory");
        __syncthreads();   // stage st visible to all; stage st^1 free

        if (kt + 1 <= ktmax) prefetchKV(st ^ 1, kt + 1);

        if (kt * 64 <= row_max) {
            const uint32_t ksb = sb + (st * KVSTG) * 2;
            const uint32_t vsb = ksb + (64 * ASTR) * 2;

            float s[8][4] = {};
            #pragma unroll
            for (int nt = 0; nt < 8; nt++) {
                #pragma unroll
                for (int jj = 0; jj < 2; jj++) {
                    uint32_t addr = ksb + 2 * ((nt * 8 + lrow) * ASTR
                                               + 32 * jj + 8 * lmat);
                    unsigned r0, r1, r2, r3;
                    LDM_X4(r0, r1, r2, r3, addr);
                    MMA_F16(s[nt], qf[2 * jj],     r0, r1);
                    MMA_F16(s[nt], qf[2 * jj + 1], r2, r3);
                }
            }

            if (kt * 64 + 63 > row_min) {
                int colb = kt * 64 + 2 * t;
                #pragma unroll
                for (int nt = 0; nt < 8; nt++) {
                    int c0 = colb + nt * 8, c1 = c0 + 1;
                    if (c0 > r0g)     s[nt][0] = -1e30f;
                    if (c1 > r0g)     s[nt][1] = -1e30f;
                    if (c0 > r0g + 8) s[nt][2] = -1e30f;
                    if (c1 > r0g + 8) s[nt][3] = -1e30f;
                }
            }

            float mx0 = -1e30f, mx1 = -1e30f;
            #pragma unroll
            for (int nt = 0; nt < 8; nt++) {
                mx0 = fmaxf(mx0, fmaxf(s[nt][0], s[nt][1]));
                mx1 = fmaxf(mx1, fmaxf(s[nt][2], s[nt][3]));
            }
            mx0 = fmaxf(mx0, __shfl_xor_sync(0xffffffffu, mx0, 1));
            mx0 = fmaxf(mx0, __shfl_xor_sync(0xffffffffu, mx0, 2));
            mx1 = fmaxf(mx1, __shfl_xor_sync(0xffffffffu, mx1, 1));
            mx1 = fmaxf(mx1, __shfl_xor_sync(0xffffffffu, mx1, 2));

            float mn0 = fmaxf(m0, mx0), mn1 = fmaxf(m1, mx1);
            float cr0 = __expf(m0 - mn0), cr1 = __expf(m1 - mn1);
            float sum0 = 0.0f, sum1 = 0.0f;
            #pragma unroll
            for (int nt = 0; nt < 8; nt++) {
                s[nt][0] = __expf(s[nt][0] - mn0);
                s[nt][1] = __expf(s[nt][1] - mn0);
                s[nt][2] = __expf(s[nt][2] - mn1);
                s[nt][3] = __expf(s[nt][3] - mn1);
                sum0 += s[nt][0] + s[nt][1];
                sum1 += s[nt][2] + s[nt][3];
            }
            sum0 += __shfl_xor_sync(0xffffffffu, sum0, 1);
            sum0 += __shfl_xor_sync(0xffffffffu, sum0, 2);
            sum1 += __shfl_xor_sync(0xffffffffu, sum1, 1);
            sum1 += __shfl_xor_sync(0xffffffffu, sum1, 2);

            l0 = l0 * cr0 + sum0;  l1 = l1 * cr1 + sum1;
            m0 = mn0;              m1 = mn1;
            #pragma unroll
            for (int nt = 0; nt < 8; nt++) {
                o[nt][0] *= cr0; o[nt][1] *= cr0;
                o[nt][2] *= cr1; o[nt][3] *= cr1;
            }

            unsigned af[4][4];
            #pragma unroll
            for (int j = 0; j < 4; j++) {
                af[j][0] = pack_h2(s[2 * j][0],     s[2 * j][1]);
                af[j][1] = pack_h2(s[2 * j][2],     s[2 * j][3]);
                af[j][2] = pack_h2(s[2 * j + 1][0], s[2 * j + 1][1]);
                af[j][3] = pack_h2(s[2 * j + 1][2], s[2 * j + 1][3]);
            }

            #pragma unroll
            for (int nt = 0; nt < 8; nt++) {
                #pragma unroll
                for (int jj = 0; jj < 2; jj++) {
                    uint32_t addr = vsb + 2 * ((32 * jj + 8 * lmat + lrow) * ASTR
                                               + 8 * nt);
                    unsigned r0, r1, r2, r3;
                    LDM_X4_T(r0, r1, r2, r3, addr);
                    MMA_F16(o[nt], af[2 * jj],     r0, r1);
                    MMA_F16(o[nt], af[2 * jj + 1], r2, r3);
                }
            }
        }
    }

    float inv0 = 1.0f / l0, inv1 = 1.0f / l1;
    float* op0 = out + ((size_t)b * T_ + q0 + lr) * 64;
    float* op1 = out + ((size_t)b * T_ + q0 + lr + 8) * 64;
    #pragma unroll
    for (int nt = 0; nt < 8; nt++) {
        int col = nt * 8 + 2 * t;
        *(float2*)&op0[col] = make_float2(o[nt][0] * inv0, o[nt][1] * inv0);
        *(float2*)&op1[col] = make_float2(o[nt][2] * inv1, o[nt][3] * inv1);
    }
}

// ---------------------------------------------------------------------------
extern "C" void kernel_launch(void* const* d_in, const int* in_sizes, int n_in,
                              void* d_out, int out_size)
{
    const float* x  = (const float*)d_in[0];
    const float* Wq = (const float*)d_in[1];
    const float* Wk = (const float*)d_in[2];
    const float* Wv = (const float*)d_in[3];
    float* out = (float*)d_out;

    wh_kernel<<<288, 256>>>(Wq, Wk, Wv);

    cudaFuncSetAttribute(qkv_fp16_kernel,
                         cudaFuncAttributeMaxDynamicSharedMemorySize,
                         QKV_SMEM_BYTES);
    qkv_fp16_kernel<<<M_ / 64, 256, QKV_SMEM_BYTES>>>(x);

    cudaFuncSetAttribute(attn_fp16_kernel,
                         cudaFuncAttributeMaxDynamicSharedMemorySize,
                         ATTN_SMEM_BYTES);
    attn_fp16_kernel<<<dim3(T_ / 128, B_), 256, ATTN_SMEM_BYTES>>>(out);
}